// round 4
// baseline (speedup 1.0000x reference)
#include <cuda_runtime.h>

// MKMMD loss, fused persistent kernel (R4: 272 CTAs, D split across 2 CTAs
// per tile for 2 CTAs/SM occupancy; distances staged in L2 slab).
// total = concat(src,tgt): N=512 rows, D=512.
// result = (10*N + 2*sum_{i<j} s_i s_j (kL2+kL1)) / B^2, s=+/-1 by half.
// bw_x = 2*S_upper_x/(N^2-N)/100 ; k = sum_{m=0..4} exp(-d/(bw*10^m))

#define DDIM  512
#define NTIL  16
#define NTILES 136
#define GRID  272           // 136 tiles x 2 D-halves
#define CH    64
#define SW    68            // 272B row stride: 16B-aligned LDS.128

typedef unsigned long long u64;

__device__ float  g_p1[GRID];
__device__ float  g_p2[GRID];
__device__ float  g_p3[GRID];
__device__ float2 g_slab[2][NTILES][1024];   // [half][tile][pair] = {l1, l2}
__device__ int    g_bar1;
__device__ int    g_bar2;

__device__ __forceinline__ u64 add2(u64 a, u64 b) {
    u64 r; asm("add.rn.f32x2 %0,%1,%2;" : "=l"(r) : "l"(a), "l"(b)); return r;
}
__device__ __forceinline__ u64 fma2(u64 a, u64 b, u64 c) {
    u64 r; asm("fma.rn.f32x2 %0,%1,%2,%3;" : "=l"(r) : "l"(a), "l"(b), "l"(c)); return r;
}
__device__ __forceinline__ float lo2(u64 a) { return __uint_as_float((unsigned)(a & 0xffffffffu)); }
__device__ __forceinline__ float hi2(u64 a) { return __uint_as_float((unsigned)(a >> 32)); }

// block reduce; valid result on thread 0 only
__device__ __forceinline__ float bred(float v, float* sbuf) {
    const int tid = threadIdx.x;
#pragma unroll
    for (int o = 16; o; o >>= 1) v += __shfl_down_sync(0xffffffffu, v, o);
    __syncthreads();
    if ((tid & 31) == 0) sbuf[tid >> 5] = v;
    __syncthreads();
    float r = 0.0f;
    if (tid == 0) {
#pragma unroll
        for (int w = 0; w < 8; ++w) r += sbuf[w];
    }
    return r;
}

// one chunk (64 k-values) of packed L1/L2 accumulation
__device__ __forceinline__ void compute_chunk(
    const float* __restrict__ As, const float* __restrict__ Bs,
    int ty, int tx, u64 l1a[2][2], u64 l2a[2][2])
{
    const ulonglong2* __restrict__ a0 = (const ulonglong2*)(As + ty * SW);
    const ulonglong2* __restrict__ a1 = (const ulonglong2*)(As + (ty + 16) * SW);
    const ulonglong2* __restrict__ b0 = (const ulonglong2*)(Bs + tx * SW);
    const ulonglong2* __restrict__ b1 = (const ulonglong2*)(Bs + (tx + 16) * SW);

#pragma unroll
    for (int q = 0; q < CH / 4; ++q) {          // 4 k per q, imm-offset LDS.128
        ulonglong2 A0 = a0[q], A1 = a1[q], B0 = b0[q], B1 = b1[q];
#pragma unroll
        for (int h = 0; h < 2; ++h) {
            u64 av[2], bv[2];
            av[0] = h ? A0.y : A0.x;
            av[1] = h ? A1.y : A1.x;
            bv[0] = h ? B0.y : B0.x;
            bv[1] = h ? B1.y : B1.x;
#pragma unroll
            for (int u = 0; u < 2; ++u)
#pragma unroll
                for (int v = 0; v < 2; ++v) {
                    u64 d  = add2(av[u], bv[v]);          // a - b (b pre-negated)
                    u64 ad = d & 0x7fffffff7fffffffULL;   // packed |d| (alu pipe)
                    l2a[u][v] = fma2(d, d, l2a[u][v]);
                    l1a[u][v] = add2(l1a[u][v], ad);
                }
        }
    }
}

__global__ __launch_bounds__(256, 2) void mkmmd_kernel(
    const float* __restrict__ src, const float* __restrict__ tgt,
    float* __restrict__ out)
{
    __shared__ __align__(16) float As[2][32][SW];
    __shared__ __align__(16) float Bs[2][32][SW];   // NEGATED B rows
    __shared__ float sbuf[8];
    __shared__ float siv[10];

    const int tid = threadIdx.x;
    const int tx = tid & 15;
    const int ty = tid >> 4;

    const int tile = blockIdx.x >> 1;
    const int half = blockIdx.x & 1;

    // decode upper-triangle tile (ti <= tj) over 16x16 grid
    int t = tile, ti = 0;
    while (t >= NTIL - ti) { t -= NTIL - ti; ti++; }
    const int tj = ti + t;
    const int i0 = ti * 32, j0 = tj * 32;
    const float* Ap = (i0 < 256) ? src + (size_t)i0 * DDIM : tgt + (size_t)(i0 - 256) * DDIM;
    const float* Bp = (j0 < 256) ? src + (size_t)j0 * DDIM : tgt + (size_t)(j0 - 256) * DDIM;

    const int lr = tid >> 4;            // load rows lr, lr+16
    const int lc = (tid & 15) * 4;      // float4 column
    const int kb0 = half * (DDIM / 2);  // this CTA's 256-wide D slice

    u64 l1a[2][2] = {{0ull, 0ull}, {0ull, 0ull}};
    u64 l2a[2][2] = {{0ull, 0ull}, {0ull, 0ull}};

    float4 pa0 = *(const float4*)(Ap + lr * DDIM + kb0 + lc);
    float4 pa1 = *(const float4*)(Ap + (lr + 16) * DDIM + kb0 + lc);
    float4 pb0 = *(const float4*)(Bp + lr * DDIM + kb0 + lc);
    float4 pb1 = *(const float4*)(Bp + (lr + 16) * DDIM + kb0 + lc);

    const int NCHUNK = (DDIM / 2) / CH;   // 4
    for (int c = 0; c < NCHUNK; ++c) {
        const int p = c & 1;
        *(float4*)&As[p][lr][lc]      = pa0;
        *(float4*)&As[p][lr + 16][lc] = pa1;
        *(float4*)&Bs[p][lr][lc]      = make_float4(-pb0.x, -pb0.y, -pb0.z, -pb0.w);
        *(float4*)&Bs[p][lr + 16][lc] = make_float4(-pb1.x, -pb1.y, -pb1.z, -pb1.w);
        __syncthreads();

        if (c < NCHUNK - 1) {
            const int kb = kb0 + (c + 1) * CH;
            pa0 = *(const float4*)(Ap + lr * DDIM + kb + lc);
            pa1 = *(const float4*)(Ap + (lr + 16) * DDIM + kb + lc);
            pb0 = *(const float4*)(Bp + lr * DDIM + kb + lc);
            pb1 = *(const float4*)(Bp + (lr + 16) * DDIM + kb + lc);
        }
        compute_chunk(&As[p][0][0], &Bs[p][0][0], ty, tx, l1a, l2a);
    }

    // collapse packed halves; write slab; masked partial sums for bandwidth
    float s1 = 0.0f, s2 = 0.0f;
#pragma unroll
    for (int u = 0; u < 2; ++u)
#pragma unroll
        for (int v = 0; v < 2; ++v) {
            float l1 = lo2(l1a[u][v]) + hi2(l1a[u][v]);
            float l2 = lo2(l2a[u][v]) + hi2(l2a[u][v]);
            const int il = ty + 16 * u;
            const int jl = tx + 16 * v;
            g_slab[half][tile][il * 32 + jl] = make_float2(l1, l2);
            if (ti < tj || jl > il) { s1 += l1; s2 += l2; }
        }

    {
        float r1 = bred(s1, sbuf);
        float r2 = bred(s2, sbuf);
        if (tid == 0) {
            g_p1[blockIdx.x] = r1;
            g_p2[blockIdx.x] = r2;
            __threadfence();
            atomicAdd(&g_bar1, 1);
            while (*(volatile int*)&g_bar1 < GRID) {}
            __threadfence();
        }
        __syncthreads();   // release whole CTA; all slabs + partials visible
    }

    // bandwidth ladder from the 272 partials (fixed order -> deterministic)
    {
        float v1 = 0.0f, v2 = 0.0f;
        for (int j = tid; j < GRID; j += 256) {
            v1 += ((volatile float*)g_p1)[j];
            v2 += ((volatile float*)g_p2)[j];
        }
        float S1 = bred(v1, sbuf);
        float S2 = bred(v2, sbuf);
        if (tid == 0) {
            const float cc = 2.0f * 0.01f / 261632.0f;   // 2/(N^2-N)/100
            float iv1 = 1.0f / (S1 * cc);
            float iv2 = 1.0f / (S2 * cc);
#pragma unroll
            for (int m = 0; m < 5; ++m) {
                siv[m]     = iv1;
                siv[5 + m] = iv2;
                iv1 *= 0.1f;
                iv2 *= 0.1f;
            }
        }
        __syncthreads();
    }

    // exp phase: this CTA handles pairs [512*half, 512*half+512) of its tile
    float acc = 0.0f;
#pragma unroll
    for (int w = 0; w < 2; ++w) {
        const int p = half * 512 + w * 256 + tid;
        float2 h0 = g_slab[0][tile][p];
        float2 h1 = g_slab[1][tile][p];
        const int il = p >> 5, jl = p & 31;
        if (ti < tj || jl > il) {
            float l1 = h0.x + h1.x;
            float l2 = h0.y + h1.y;
            float kv = 0.0f;
#pragma unroll
            for (int m = 0; m < 5; ++m) {
                kv += __expf(-l1 * siv[m]);
                kv += __expf(-l2 * siv[5 + m]);
            }
            acc += kv;
        }
    }

    float atot = bred(acc, sbuf);
    if (tid == 0) {
        const float sgn = ((ti < 8) == (tj < 8)) ? 1.0f : -1.0f;
        g_p3[blockIdx.x] = sgn * atot;
        __threadfence();
        int r = atomicAdd(&g_bar2, 1);
        if (r == GRID - 1) {
            // 272nd arriver: every CTA is past its bar1 spin -> safe to reset
            __threadfence();
            float s = 0.0f;
            for (int q = 0; q < GRID; ++q) s += ((volatile float*)g_p3)[q];
            out[0] = 5120.0f / 65536.0f + s * (2.0f / 65536.0f);
            g_bar1 = 0;
            g_bar2 = 0;
            __threadfence();
        }
    }
}

extern "C" void kernel_launch(void* const* d_in, const int* in_sizes, int n_in,
                              void* d_out, int out_size) {
    const float* src = (const float*)d_in[0];
    const float* tgt = (const float*)d_in[1];
    float* out = (float*)d_out;
    mkmmd_kernel<<<GRID, 256>>>(src, tgt, out);
}